// round 8
// baseline (speedup 1.0000x reference)
#include <cuda_runtime.h>
#include <cuda_bf16.h>

// Problem constants (match reference)
#define BB   64
#define CC   2
#define LL   64
#define NBIN 16
#define NVOX (LL*LL*LL)        // 262144
#define NPAIR (BB*CC)          // 128
#define NDENSE 25              // only ax,az in 0..4 ever occur
#define DSTRIDE 32             // padded partial stride per block
#define EPSV 1e-5f

// tan^2(22a degrees), a = 1..4 (f32, same literals as the validated runtime kernel)
#define T1Q 0.16323719f
#define T2Q 0.93255481f
#define T3Q 5.0446812f
#define T4Q 820.03500f

#define SPLIT 8                        // blocks per (b,c) pair
#define CHUNK (NVOX / SPLIT)           // 32768 elements
#define BTHREADS 256

// ---------------------------------------------------------------------------
// COMPILE-TIME bin table. Uses the exact same f32 threshold arithmetic as the
// previously-validated runtime builder (IEEE f32 in constexpr == runtime FMUL/
// FSETP), so the table is bit-identical — but costs 0 us at runtime.
//   ax = #{a : j^2+k^2 >= i^2 tan^2(22a)},  az = #{a : k^2 >= (i^2+j^2) tan^2(22a)}
// ---------------------------------------------------------------------------
struct BinTable { alignas(16) unsigned char b[NVOX]; };

static constexpr BinTable make_bins() {
    BinTable t{};
    for (int i = 0; i < LL; i++) {
        float fi = (float)i;
        float ii = fi * fi;
        float a1 = ii * T1Q, a2 = ii * T2Q, a3 = ii * T3Q, a4 = ii * T4Q;
        for (int j = 0; j < LL; j++) {
            float fj = (float)j;
            float jj = fj * fj;
            float ij = ii + jj;
            float z1 = ij * T1Q, z2 = ij * T2Q, z3 = ij * T3Q, z4 = ij * T4Q;
            for (int k = 0; k < LL; k++) {
                float fk = (float)k;
                float kk = fk * fk;
                float jk = jj + kk;
                int ax = (jk >= a1) + (jk >= a2) + (jk >= a3) + (jk >= a4);
                int az = (kk >= z1) + (kk >= z2) + (kk >= z3) + (kk >= z4);
                t.b[(i << 12) | (j << 6) | k] = (unsigned char)(ax * 5 + az);
            }
        }
    }
    return t;
}

__device__ constexpr BinTable g_btab = make_bins();

// Per-block partial sums: plain stores (no atomics, no zero-init needed —
// every slot 0..24 is written by its owning block every launch).
__device__ float g_partial[NPAIR * SPLIT * DSTRIDE];   // 128 KB

// ---------------------------------------------------------------------------
// Kernel B: streaming weighted histogram, fully BRANCHLESS hot loop.
//   - per-thread private histogram column: hist[bin*256 + t]
//     bank = t mod 32  ->  conflict-free for ANY bin pattern across lanes
//   - 8 elements per thread-iteration: 2x LDG.128 (__ldcs, streaming) + 1x
//     LDG.64 of 8 bin bytes (L2-resident static table)
//   - SPLIT=8 -> 1024 CTAs = ONE wave at 8 CTA/SM smem occupancy
//   - mag recomputed inline with __fsqrt_rn (bit-exact vs reference)
//   - flush: tree-reduce + 25 plain stores to this block's private slot
// ---------------------------------------------------------------------------
__global__ __launch_bounds__(BTHREADS) void accumulate_kernel(const float* __restrict__ x) {
    __shared__ float hist[NDENSE * BTHREADS];     // 25.6 KB
    const int t = threadIdx.x;
    #pragma unroll
    for (int i = 0; i < NDENSE; i++) hist[i * BTHREADS + t] = 0.0f;
    // each thread touches only column t -> no sync needed before the loop
    float* __restrict__ h = hist + t;

    const int pair  = blockIdx.x >> 3;            // b*C + c
    const int part  = blockIdx.x & (SPLIT - 1);
    const int vbase = part * CHUNK;
    const float* __restrict__ xp = x + (size_t)pair * NVOX + vbase;
    const unsigned char* __restrict__ bp = g_btab.b + vbase;

    // CHUNK/(256*8) = 16 iterations
    #pragma unroll 4
    for (int off = t * 8; off < CHUNK; off += BTHREADS * 8) {
        float4 xa = __ldcs(reinterpret_cast<const float4*>(xp + off));
        float4 xb = __ldcs(reinterpret_cast<const float4*>(xp + off + 4));
        uint2  bq = *reinterpret_cast<const uint2*>(bp + off);

        int v = vbase + off;                      // off%8==0 -> k..k+7 in-row
        float fi = (float)(v >> 12);
        float fj = (float)((v >> 6) & 63);
        float fk = (float)(v & 63);
        float s2 = fi*fi + fj*fj;
        // mag_u = sqrt(s2 + (fk+u)^2), one FFMA + MUFU each
        float f1 = fk + 1.0f, f2 = fk + 2.0f, f3 = fk + 3.0f;
        float f4 = fk + 4.0f, f5 = fk + 5.0f, f6 = fk + 6.0f, f7 = fk + 7.0f;
        float m0 = __fsqrt_rn(fmaf(fk, fk, s2));
        float m1 = __fsqrt_rn(fmaf(f1, f1, s2));
        float m2 = __fsqrt_rn(fmaf(f2, f2, s2));
        float m3 = __fsqrt_rn(fmaf(f3, f3, s2));
        float m4 = __fsqrt_rn(fmaf(f4, f4, s2));
        float m5 = __fsqrt_rn(fmaf(f5, f5, s2));
        float m6 = __fsqrt_rn(fmaf(f6, f6, s2));
        float m7 = __fsqrt_rn(fmaf(f7, f7, s2));

        // row offset = bin*256 = byte<<8; h = hist + t (private column)
        h[(( bq.x        & 0xffu) << 8)] += xa.x * m0;
        h[(((bq.x >>  8) & 0xffu) << 8)] += xa.y * m1;
        h[(((bq.x >> 16) & 0xffu) << 8)] += xa.z * m2;
        h[(( bq.x >> 24         ) << 8)] += xa.w * m3;
        h[(( bq.y        & 0xffu) << 8)] += xb.x * m4;
        h[(((bq.y >>  8) & 0xffu) << 8)] += xb.y * m5;
        h[(((bq.y >> 16) & 0xffu) << 8)] += xb.z * m6;
        h[(( bq.y >> 24         ) << 8)] += xb.w * m7;
    }

    __syncthreads();

    // Flush: 8 warps; warp w handles bins {w, w+8, w+16, w+24};
    // plain store into this block's private partial slot (no atomics).
    const int warp = t >> 5, lane = t & 31;
    const unsigned full = 0xffffffffu;
    for (int bin = warp; bin < NDENSE; bin += 8) {
        const float* row = &hist[bin * BTHREADS];
        float s = 0.0f;
        #pragma unroll
        for (int j = 0; j < 8; j++) s += row[lane + 32*j];
        #pragma unroll
        for (int d = 16; d; d >>= 1) s += __shfl_down_sync(full, s, d);
        if (lane == 0) g_partial[blockIdx.x * DSTRIDE + bin] = s;
    }
}

// ---------------------------------------------------------------------------
// Kernel C: per-channel group norm. 32 blocks: 16 per channel; each block
// redundantly computes the channel stats (summing the 8 per-block partials
// per (b,c,bin)), then writes a disjoint 1024-element output slice.
// Two-pass mean/var; zero bins enter variance as (16384 - 64*25)*mean^2.
// ---------------------------------------------------------------------------
#define CSEG 16                        // output segments per channel

__global__ __launch_bounds__(256) void gn_kernel(const float* __restrict__ gamma,
                                                 const float* __restrict__ beta,
                                                 float* __restrict__ out) {
    const int c   = blockIdx.x & 1;
    const int seg = blockIdx.x >> 1;
    const int t = threadIdx.x;
    const int lane = t & 31, warp = t >> 5;
    const unsigned full = 0xffffffffu;

    __shared__ float red[8];
    __shared__ float s_mean, s_rs;

    float vals[7];                      // ceil(1600/256) = 7 slots
    float sum = 0.0f;
    #pragma unroll
    for (int i = 0; i < 7; i++) {
        int idx = i * 256 + t;
        float g = 0.0f;
        if (idx < BB * NDENSE) {
            int b = idx / NDENSE, d = idx % NDENSE;
            const float* p = &g_partial[((b * CC + c) * SPLIT) * DSTRIDE + d];
            #pragma unroll
            for (int q = 0; q < SPLIT; q++) g += p[q * DSTRIDE];
        }
        vals[i] = g;
        sum += g;
    }
    #pragma unroll
    for (int d = 16; d; d >>= 1) sum += __shfl_down_sync(full, sum, d);
    if (lane == 0) red[warp] = sum;
    __syncthreads();
    if (t == 0) {
        float tot = 0.0f;
        #pragma unroll
        for (int w = 0; w < 8; w++) tot += red[w];
        s_mean = tot * (1.0f / (BB * NBIN * NBIN));
    }
    __syncthreads();
    float mean = s_mean;

    float vs = 0.0f;
    #pragma unroll
    for (int i = 0; i < 7; i++) {
        int idx = i * 256 + t;
        if (idx < BB * NDENSE) {
            float d = vals[i] - mean;
            vs = fmaf(d, d, vs);
        }
    }
    #pragma unroll
    for (int d = 16; d; d >>= 1) vs += __shfl_down_sync(full, vs, d);
    __syncthreads();
    if (lane == 0) red[warp] = vs;
    __syncthreads();
    if (t == 0) {
        float tot = 0.0f;
        #pragma unroll
        for (int w = 0; w < 8; w++) tot += red[w];
        tot += (float)(BB * NBIN * NBIN - BB * NDENSE) * s_mean * s_mean;
        float var = tot * (1.0f / (BB * NBIN * NBIN));
        s_rs = rsqrtf(var + EPSV);
    }
    __syncthreads();
    float rs = s_rs;
    float ga = gamma[c], be = beta[c];

    // this block writes outputs [seg*1024, (seg+1)*1024) of channel c
    {
        int idx = seg * 1024 + t;                 // 4 iters of 256
        #pragma unroll
        for (int i = 0; i < 4; i++, idx += 256) {
            int b = idx >> 8, s = idx & 255;
            int ax = s >> 4, az = s & 15;
            float g = 0.0f;
            if (ax < 5 && az < 5) {
                const float* p = &g_partial[((b * CC + c) * SPLIT) * DSTRIDE + ax * 5 + az];
                #pragma unroll
                for (int q = 0; q < SPLIT; q++) g += p[q * DSTRIDE];
            }
            out[(b * CC + c) * 256 + s] = (g - mean) * rs * ga + be;
        }
    }
}

// ---------------------------------------------------------------------------
extern "C" void kernel_launch(void* const* d_in, const int* in_sizes, int n_in,
                              void* d_out, int out_size) {
    const float* x     = (const float*)d_in[0];   // [64, 2*64^3]
    const float* gamma = (const float*)d_in[1];   // [2]
    const float* beta  = (const float*)d_in[2];   // [2]
    float* out = (float*)d_out;                   // [64,2,16,16] f32

    accumulate_kernel<<<NPAIR * SPLIT, BTHREADS>>>(x);
    gn_kernel<<<CC * CSEG, 256>>>(gamma, beta, out);
}